// round 2
// baseline (speedup 1.0000x reference)
#include <cuda_runtime.h>
#include <math.h>

#define SLEN  1024
#define BATCH 16
#define EDIM  300
#define HDIM  128
#define G3    384
#define NHEADS 4
#define DDIM  256

// ---------------- scratch (device globals; no allocation allowed) ----------
__device__ __align__(16) float g_gx[2][SLEN][BATCH][G3];        // 50 MB
__device__ __align__(16) float g_rh[BATCH][SLEN][DDIM];         // 16 MB
__device__ __align__(16) float g_q[BATCH*NHEADS][SLEN][DDIM];   // 64 MB
__device__ __align__(16) float g_alpha[BATCH*NHEADS][SLEN][SLEN]; // 268 MB
__device__ __align__(16) float g_alphaw[BATCH][SLEN][SLEN];     // 64 MB
__device__ __align__(16) float g_sacc[BATCH][SLEN][DDIM];       // 16 MB
__device__ int g_is64;

// ---------------- dtype detection for `review` (int32 vs int64) ------------
// If the tensor is int64, every high 32-bit word is zero (tokens < 32000).
// If int32, the "high words" are actually other random tokens -> nonzero.
__global__ void detect_kernel(const int* __restrict__ rv) {
    __shared__ int any;
    if (threadIdx.x == 0) any = 0;
    __syncthreads();
    int nz = 0;
    for (int j = threadIdx.x; j < BATCH * SLEN; j += blockDim.x)
        nz |= (rv[2 * j + 1] != 0);
    if (nz) atomicOr(&any, 1);
    __syncthreads();
    if (threadIdx.x == 0) g_is64 = any ? 0 : 1;
}

// ---------------- shared tiled-GEMM inner product ---------------------------
__device__ __forceinline__ void mm16(const float (*As)[68], const float (*Bs)[68],
                                     float acc[4][4], int ty, int tx) {
#pragma unroll
    for (int k = 0; k < 16; k++) {
        float4 a = *(const float4*)(&As[k][ty * 4]);
        float4 b = *(const float4*)(&Bs[k][tx * 4]);
        float ar[4] = {a.x, a.y, a.z, a.w};
        float br[4] = {b.x, b.y, b.z, b.w};
#pragma unroll
        for (int i = 0; i < 4; i++)
#pragma unroll
            for (int j = 0; j < 4; j++)
                acc[i][j] += ar[i] * br[j];
    }
}

// ---------------- K1: embedding gather + input-gate GEMM --------------------
// gx[dir][s][b][n] = emb[tok(b, s_dir)] . w_ih_dir[n] + b_ih_dir[n]
__global__ __launch_bounds__(256) void gx_kernel(
    const void* __restrict__ review, const float* __restrict__ emb,
    const float* __restrict__ w_ih_f, const float* __restrict__ b_ih_f,
    const float* __restrict__ w_ih_b, const float* __restrict__ b_ih_b)
{
    __shared__ __align__(16) float As[16][68];
    __shared__ __align__(16) float Bs[16][68];
    int dir = blockIdx.z;
    const float* W    = dir ? w_ih_b : w_ih_f;
    const float* bias = dir ? b_ih_b : b_ih_f;
    int tid = threadIdx.x;
    int m0 = blockIdx.y * 64, n0 = blockIdx.x * 64;
    int lr = tid >> 2, kq = (tid & 3) * 4;

    int m = m0 + lr;
    int s = m >> 4, bb = m & 15;
    int stok = dir ? (SLEN - 1 - s) : s;
    long long tok;
    if (g_is64) tok = ((const long long*)review)[bb * SLEN + stok];
    else        tok = (long long)(((const int*)review)[bb * SLEN + stok]);
    const float* arow = emb + (size_t)tok * EDIM;
    const float* brow = W + (size_t)(n0 + lr) * EDIM;

    int ty = tid >> 4, tx = tid & 15;
    float acc[4][4] = {};
    for (int k0 = 0; k0 < EDIM; k0 += 16) {
#pragma unroll
        for (int i = 0; i < 4; i++) {
            int k = k0 + kq + i;
            As[kq + i][lr] = (k < EDIM) ? arow[k] : 0.f;
            Bs[kq + i][lr] = (k < EDIM) ? brow[k] : 0.f;
        }
        __syncthreads();
        mm16(As, Bs, acc, ty, tx);
        __syncthreads();
    }
#pragma unroll
    for (int i = 0; i < 4; i++) {
        int mm = m0 + ty * 4 + i;
        int ss = mm >> 4, bv = mm & 15;
#pragma unroll
        for (int j = 0; j < 4; j++) {
            int n = n0 + tx * 4 + j;
            g_gx[dir][ss][bv][n] = acc[i][j] + bias[n];
        }
    }
}

// ---------------- K2: GRU scan (one CTA per direction x batch) --------------
__global__ __launch_bounds__(512, 1) void gru_kernel(
    const float* __restrict__ w_hh_f, const float* __restrict__ b_hh_f,
    const float* __restrict__ w_hh_b, const float* __restrict__ b_hh_b)
{
    int dir = blockIdx.x >> 4;
    int b   = blockIdx.x & 15;
    const float* w_hh = dir ? w_hh_b : w_hh_f;
    const float* b_hh = dir ? b_hh_b : b_hh_f;

    int t  = threadIdx.x;     // 512 threads
    int jj = t >> 2;          // hidden unit 0..127
    int r4 = t & 3;           // k-quarter 0..3
    int k0 = r4 * 32;

    float wr[32], wz[32], wn[32];
#pragma unroll
    for (int i = 0; i < 32; i++) {
        wr[i] = w_hh[(jj)       * HDIM + k0 + i];
        wz[i] = w_hh[(HDIM + jj) * HDIM + k0 + i];
        wn[i] = w_hh[(2*HDIM+jj) * HDIM + k0 + i];
    }
    float bhr = 0.f, bhz = 0.f, bhn = 0.f, gxr = 0.f, gxz = 0.f, gxn = 0.f;
    const float* gx = &g_gx[dir][0][b][0];
    const int GXS = BATCH * G3;
    if (r4 == 0) {
        bhr = b_hh[jj]; bhz = b_hh[HDIM + jj]; bhn = b_hh[2*HDIM + jj];
        gxr = gx[jj]; gxz = gx[HDIM + jj]; gxn = gx[2*HDIM + jj];
    }

    __shared__ __align__(16) float h_sm[HDIM];
    if (t < HDIM) h_sm[t] = 0.f;
    __syncthreads();

    for (int sc = 0; sc < SLEN; sc++) {
        float ar = 0.f, az = 0.f, an = 0.f;
#pragma unroll
        for (int i = 0; i < 32; i += 4) {
            float4 v = *(const float4*)&h_sm[k0 + i];
            ar += wr[i]   * v.x; az += wz[i]   * v.x; an += wn[i]   * v.x;
            ar += wr[i+1] * v.y; az += wz[i+1] * v.y; an += wn[i+1] * v.y;
            ar += wr[i+2] * v.z; az += wz[i+2] * v.z; an += wn[i+2] * v.z;
            ar += wr[i+3] * v.w; az += wz[i+3] * v.w; an += wn[i+3] * v.w;
        }
        float hold = 0.f;
        if (r4 == 0) hold = h_sm[jj];

        ar += __shfl_xor_sync(0xffffffffu, ar, 1);
        ar += __shfl_xor_sync(0xffffffffu, ar, 2);
        az += __shfl_xor_sync(0xffffffffu, az, 1);
        az += __shfl_xor_sync(0xffffffffu, az, 2);
        an += __shfl_xor_sync(0xffffffffu, an, 1);
        an += __shfl_xor_sync(0xffffffffu, an, 2);

        __syncthreads();   // all reads of h_sm done
        if (r4 == 0) {
            float r = 1.f / (1.f + __expf(-(gxr + ar + bhr)));
            float z = 1.f / (1.f + __expf(-(gxz + az + bhz)));
            float n = tanhf(gxn + r * (an + bhn));
            float hnew = (1.f - z) * n + z * hold;
            h_sm[jj] = hnew;
            int sorig = dir ? (SLEN - 1 - sc) : sc;
            g_rh[b][sorig][dir * HDIM + jj] = hnew;
            if (sc + 1 < SLEN) {
                const float* g2 = gx + (size_t)(sc + 1) * GXS;
                gxr = g2[jj]; gxz = g2[HDIM + jj]; gxn = g2[2*HDIM + jj];
            }
        }
        __syncthreads();   // new h visible
    }
}

// ---------------- K3a: q = rh @ Wm[h]  (per b,h) ----------------------------
__global__ __launch_bounds__(256) void q_kernel(const float* __restrict__ weight_m)
{
    __shared__ __align__(16) float As[16][68];
    __shared__ __align__(16) float Bs[16][68];
    int z = blockIdx.z;  int b = z >> 2, h = z & 3;
    int tid = threadIdx.x;
    int m0 = blockIdx.y * 64, n0 = blockIdx.x * 64;
    int lr = tid >> 2, kq = (tid & 3) * 4;        // A transposed store
    int bkr = tid >> 4, bn4 = (tid & 15) * 4;     // B NN store
    const float* A  = &g_rh[b][0][0];
    const float* Bm = weight_m + (size_t)h * DDIM * DDIM;
    int ty = tid >> 4, tx = tid & 15;
    float acc[4][4] = {};
    for (int k0 = 0; k0 < DDIM; k0 += 16) {
        float4 av = *(const float4*)&A[(m0 + lr) * DDIM + k0 + kq];
        As[kq+0][lr] = av.x; As[kq+1][lr] = av.y; As[kq+2][lr] = av.z; As[kq+3][lr] = av.w;
        *(float4*)&Bs[bkr][bn4] = *(const float4*)&Bm[(k0 + bkr) * DDIM + n0 + bn4];
        __syncthreads();
        mm16(As, Bs, acc, ty, tx);
        __syncthreads();
    }
#pragma unroll
    for (int i = 0; i < 4; i++) {
        int mm = m0 + ty * 4 + i;
        *(float4*)&g_q[z][mm][n0 + tx * 4] =
            make_float4(acc[i][0], acc[i][1], acc[i][2], acc[i][3]);
    }
}

// ---------------- K3b: scores = q @ rh^T  (per b,h) -------------------------
__global__ __launch_bounds__(256) void scores_kernel()
{
    __shared__ __align__(16) float As[16][68];
    __shared__ __align__(16) float Bs[16][68];
    int z = blockIdx.z;  int b = z >> 2;
    int tid = threadIdx.x;
    int m0 = blockIdx.y * 64, n0 = blockIdx.x * 64;
    int lr = tid >> 2, kq = (tid & 3) * 4;
    const float* A = &g_q[z][0][0];
    const float* B = &g_rh[b][0][0];
    int ty = tid >> 4, tx = tid & 15;
    float acc[4][4] = {};
    for (int k0 = 0; k0 < DDIM; k0 += 16) {
        float4 av = *(const float4*)&A[(m0 + lr) * DDIM + k0 + kq];
        As[kq+0][lr] = av.x; As[kq+1][lr] = av.y; As[kq+2][lr] = av.z; As[kq+3][lr] = av.w;
        float4 bv = *(const float4*)&B[(n0 + lr) * DDIM + k0 + kq];
        Bs[kq+0][lr] = bv.x; Bs[kq+1][lr] = bv.y; Bs[kq+2][lr] = bv.z; Bs[kq+3][lr] = bv.w;
        __syncthreads();
        mm16(As, Bs, acc, ty, tx);
        __syncthreads();
    }
#pragma unroll
    for (int i = 0; i < 4; i++) {
        int mm = m0 + ty * 4 + i;
        *(float4*)&g_alpha[z][mm][n0 + tx * 4] =
            make_float4(acc[i][0], acc[i][1], acc[i][2], acc[i][3]);
    }
}

// ---------------- K3c: masked softmax over t + head-weight folding ----------
__device__ __forceinline__ float block_max(float v, float* red) {
#pragma unroll
    for (int o = 16; o; o >>= 1) v = fmaxf(v, __shfl_xor_sync(0xffffffffu, v, o));
    if ((threadIdx.x & 31) == 0) red[threadIdx.x >> 5] = v;
    __syncthreads();
    float r = red[0];
#pragma unroll
    for (int w = 1; w < 8; w++) r = fmaxf(r, red[w]);
    __syncthreads();
    return r;
}
__device__ __forceinline__ float block_sum(float v, float* red) {
#pragma unroll
    for (int o = 16; o; o >>= 1) v += __shfl_xor_sync(0xffffffffu, v, o);
    if ((threadIdx.x & 31) == 0) red[threadIdx.x >> 5] = v;
    __syncthreads();
    float r = red[0];
#pragma unroll
    for (int w = 1; w < 8; w++) r += red[w];
    __syncthreads();
    return r;
}

__global__ __launch_bounds__(256) void softmax_kernel(
    const float* __restrict__ mask, const float* __restrict__ wt_w)
{
    int bs = blockIdx.x;
    int b = bs >> 10, s = bs & 1023;
    int tid = threadIdx.x;
    __shared__ float smadd[SLEN];
    __shared__ float red[8];
    for (int i = tid; i < SLEN; i += 256)
        smadd[i] = (mask[b * SLEN + i] - 1.0f) * 1e11f;
    __syncthreads();

    float accw[4] = {0.f, 0.f, 0.f, 0.f};
    for (int h = 0; h < NHEADS; h++) {
        const float* row = &g_alpha[b * NHEADS + h][s][0];
        float v[4];
        float m = -INFINITY;
#pragma unroll
        for (int i = 0; i < 4; i++) {
            v[i] = row[tid + 256 * i] + smadd[tid + 256 * i];
            m = fmaxf(m, v[i]);
        }
        m = block_max(m, red);
        float ssum = 0.f;
#pragma unroll
        for (int i = 0; i < 4; i++) { v[i] = __expf(v[i] - m); ssum += v[i]; }
        ssum = block_sum(ssum, red);
        float w = wt_w[h] / ssum;
#pragma unroll
        for (int i = 0; i < 4; i++) accw[i] += w * v[i];
    }
    float* o = &g_alphaw[b][s][0];
#pragma unroll
    for (int i = 0; i < 4; i++) o[tid + 256 * i] = accw[i];
}

// ---------------- K3d: sacc = alphaw @ rh  (per b) --------------------------
__global__ __launch_bounds__(256) void out_kernel()
{
    __shared__ __align__(16) float As[16][68];
    __shared__ __align__(16) float Bs[16][68];
    int b = blockIdx.z;
    int tid = threadIdx.x;
    int m0 = blockIdx.y * 64, n0 = blockIdx.x * 64;
    int lr = tid >> 2, kq = (tid & 3) * 4;
    int bkr = tid >> 4, bn4 = (tid & 15) * 4;
    const float* A = &g_alphaw[b][0][0];
    const float* B = &g_rh[b][0][0];
    int ty = tid >> 4, tx = tid & 15;
    float acc[4][4] = {};
    for (int k0 = 0; k0 < SLEN; k0 += 16) {
        float4 av = *(const float4*)&A[(m0 + lr) * SLEN + k0 + kq];
        As[kq+0][lr] = av.x; As[kq+1][lr] = av.y; As[kq+2][lr] = av.z; As[kq+3][lr] = av.w;
        *(float4*)&Bs[bkr][bn4] = *(const float4*)&B[(k0 + bkr) * DDIM + n0 + bn4];
        __syncthreads();
        mm16(As, Bs, acc, ty, tx);
        __syncthreads();
    }
#pragma unroll
    for (int i = 0; i < 4; i++) {
        int mm = m0 + ty * 4 + i;
        *(float4*)&g_sacc[b][mm][n0 + tx * 4] =
            make_float4(acc[i][0], acc[i][1], acc[i][2], acc[i][3]);
    }
}

// ---------------- K4: final projection + log_softmax + mask -----------------
__global__ __launch_bounds__(256) void final_kernel(
    const float* __restrict__ wr_w, const float* __restrict__ wr_b,
    const float* __restrict__ wt_b, const float* __restrict__ mask,
    float* __restrict__ out)
{
    int warp = (blockIdx.x * blockDim.x + threadIdx.x) >> 5;
    if (warp >= BATCH * SLEN) return;
    int lane = threadIdx.x & 31;
    int b = warp >> 10, s = warp & 1023;
    const float* sa = &g_sacc[b][s][0];
    float tb = wt_b[0];
    float a0 = 0.f, a1 = 0.f, a2 = 0.f;
    for (int d = lane; d < DDIM; d += 32) {
        float v = sa[d] + tb;
        a0 += v * wr_w[d];
        a1 += v * wr_w[DDIM + d];
        a2 += v * wr_w[2 * DDIM + d];
    }
#pragma unroll
    for (int o = 16; o; o >>= 1) {
        a0 += __shfl_xor_sync(0xffffffffu, a0, o);
        a1 += __shfl_xor_sync(0xffffffffu, a1, o);
        a2 += __shfl_xor_sync(0xffffffffu, a2, o);
    }
    if (lane == 0) {
        a0 += wr_b[0]; a1 += wr_b[1]; a2 += wr_b[2];
        float m = fmaxf(a0, fmaxf(a1, a2));
        float lse = m + logf(expf(a0 - m) + expf(a1 - m) + expf(a2 - m));
        float mk = mask[b * SLEN + s];
        float* op = out + (size_t)(b * SLEN + s) * 3;
        op[0] = (a0 - lse) * mk;
        op[1] = (a1 - lse) * mk;
        op[2] = (a2 - lse) * mk;
    }
}

// ---------------- launch ----------------------------------------------------
extern "C" void kernel_launch(void* const* d_in, const int* in_sizes, int n_in,
                              void* d_out, int out_size)
{
    (void)in_sizes; (void)n_in; (void)out_size;
    const void*  review = d_in[0];
    const float* mask   = (const float*)d_in[2];
    const float* emb    = (const float*)d_in[3];
    const float* w_ih_f = (const float*)d_in[4];
    const float* w_hh_f = (const float*)d_in[5];
    const float* b_ih_f = (const float*)d_in[6];
    const float* b_hh_f = (const float*)d_in[7];
    const float* w_ih_b = (const float*)d_in[8];
    const float* w_hh_b = (const float*)d_in[9];
    const float* b_ih_b = (const float*)d_in[10];
    const float* b_hh_b = (const float*)d_in[11];
    const float* weight_m = (const float*)d_in[12];
    const float* wt_w   = (const float*)d_in[13];
    const float* wt_b   = (const float*)d_in[14];
    const float* wr_w   = (const float*)d_in[15];
    const float* wr_b   = (const float*)d_in[16];
    float* out = (float*)d_out;

    detect_kernel<<<1, 256>>>((const int*)review);
    gx_kernel<<<dim3(G3 / 64, (BATCH * SLEN) / 64, 2), 256>>>(
        review, emb, w_ih_f, b_ih_f, w_ih_b, b_ih_b);
    gru_kernel<<<32, 512>>>(w_hh_f, b_hh_f, w_hh_b, b_hh_b);
    q_kernel<<<dim3(DDIM / 64, SLEN / 64, BATCH * NHEADS), 256>>>(weight_m);
    scores_kernel<<<dim3(SLEN / 64, SLEN / 64, BATCH * NHEADS), 256>>>();
    softmax_kernel<<<BATCH * SLEN, 256>>>(mask, wt_w);
    out_kernel<<<dim3(DDIM / 64, SLEN / 64, BATCH), 256>>>();
    final_kernel<<<(BATCH * SLEN) / 8, 256>>>(wr_w, wr_b, wt_b, mask, out);
}

// round 3
// speedup vs baseline: 1.0901x; 1.0901x over previous
#include <cuda_runtime.h>
#include <math.h>

#define SLEN  1024
#define BATCH 16
#define EDIM  300
#define HDIM  128
#define G3    384
#define NHEADS 4
#define DDIM  256

// ---------------- scratch (device globals; no allocation allowed) ----------
__device__ __align__(16) float g_gx[2][SLEN][BATCH][G3];        // 50 MB
__device__ __align__(16) float g_rh[BATCH][SLEN][DDIM];         // 16 MB
__device__ __align__(16) float g_q[BATCH*NHEADS][SLEN][DDIM];   // 64 MB
__device__ __align__(16) float g_alpha[BATCH*NHEADS][SLEN][SLEN]; // 268 MB
__device__ __align__(16) float g_alphaw[BATCH][SLEN][SLEN];     // 64 MB
__device__ __align__(16) float g_sacc[BATCH][SLEN][DDIM];       // 16 MB
__device__ int g_is64;

// ---------------- dtype detection for `review` (int32 vs int64) ------------
__global__ void detect_kernel(const int* __restrict__ rv) {
    __shared__ int any;
    if (threadIdx.x == 0) any = 0;
    __syncthreads();
    int nz = 0;
    for (int j = threadIdx.x; j < BATCH * SLEN; j += blockDim.x)
        nz |= (rv[2 * j + 1] != 0);
    if (nz) atomicOr(&any, 1);
    __syncthreads();
    if (threadIdx.x == 0) g_is64 = any ? 0 : 1;
}

// ============ 128x128 double-buffered fp32 GEMM (8x8 microtile) =============
struct SmemGemm {
    float A[2][16][132];
    float B[2][16][132];
};

// A is [m][k] row-major (lda = row stride). If BT, B is [n][k] row-major,
// else B is [k][n] row-major. Tile is 128x128, K consumed in 16-chunks.
template<bool BT>
__device__ __forceinline__ void gemm128_run(
    SmemGemm* sm,
    const float* __restrict__ Abase, int lda,
    const float* __restrict__ Bbase, int ldb,
    int Ktiles, float acc[8][8])
{
    int tid = threadIdx.x;
    int am = tid >> 2;              // 0..63 (+64 second half)
    int ak = (tid & 3) * 4;         // k quad
    int bk = tid >> 5;              // 0..7 (+8 second half)
    int bn = (tid & 31) * 4;
    int ty = tid >> 4, tx = tid & 15;

    float4 ra0, ra1, rb0, rb1;
    // prologue: load k-tile 0
    ra0 = *(const float4*)&Abase[(size_t)am * lda + ak];
    ra1 = *(const float4*)&Abase[(size_t)(am + 64) * lda + ak];
    if (BT) {
        rb0 = *(const float4*)&Bbase[(size_t)am * ldb + ak];
        rb1 = *(const float4*)&Bbase[(size_t)(am + 64) * ldb + ak];
    } else {
        rb0 = *(const float4*)&Bbase[(size_t)bk * ldb + bn];
        rb1 = *(const float4*)&Bbase[(size_t)(bk + 8) * ldb + bn];
    }
    {   // store into buffer 0
        sm->A[0][ak+0][am] = ra0.x; sm->A[0][ak+1][am] = ra0.y;
        sm->A[0][ak+2][am] = ra0.z; sm->A[0][ak+3][am] = ra0.w;
        sm->A[0][ak+0][am+64] = ra1.x; sm->A[0][ak+1][am+64] = ra1.y;
        sm->A[0][ak+2][am+64] = ra1.z; sm->A[0][ak+3][am+64] = ra1.w;
        if (BT) {
            sm->B[0][ak+0][am] = rb0.x; sm->B[0][ak+1][am] = rb0.y;
            sm->B[0][ak+2][am] = rb0.z; sm->B[0][ak+3][am] = rb0.w;
            sm->B[0][ak+0][am+64] = rb1.x; sm->B[0][ak+1][am+64] = rb1.y;
            sm->B[0][ak+2][am+64] = rb1.z; sm->B[0][ak+3][am+64] = rb1.w;
        } else {
            *(float4*)&sm->B[0][bk][bn]     = rb0;
            *(float4*)&sm->B[0][bk + 8][bn] = rb1;
        }
    }
    __syncthreads();

    for (int t = 0; t < Ktiles; t++) {
        int cur = t & 1;
        bool more = (t + 1 < Ktiles);
        if (more) {
            int koff = (t + 1) * 16;
            ra0 = *(const float4*)&Abase[(size_t)am * lda + ak + koff];
            ra1 = *(const float4*)&Abase[(size_t)(am + 64) * lda + ak + koff];
            if (BT) {
                rb0 = *(const float4*)&Bbase[(size_t)am * ldb + ak + koff];
                rb1 = *(const float4*)&Bbase[(size_t)(am + 64) * ldb + ak + koff];
            } else {
                rb0 = *(const float4*)&Bbase[(size_t)(bk + koff) * ldb + bn];
                rb1 = *(const float4*)&Bbase[(size_t)(bk + 8 + koff) * ldb + bn];
            }
        }
#pragma unroll
        for (int k = 0; k < 16; k++) {
            float4 a0 = *(const float4*)&sm->A[cur][k][ty * 4];
            float4 a1 = *(const float4*)&sm->A[cur][k][64 + ty * 4];
            float4 b0 = *(const float4*)&sm->B[cur][k][tx * 4];
            float4 b1 = *(const float4*)&sm->B[cur][k][64 + tx * 4];
            float av[8] = {a0.x, a0.y, a0.z, a0.w, a1.x, a1.y, a1.z, a1.w};
            float bv[8] = {b0.x, b0.y, b0.z, b0.w, b1.x, b1.y, b1.z, b1.w};
#pragma unroll
            for (int i = 0; i < 8; i++)
#pragma unroll
                for (int j = 0; j < 8; j++)
                    acc[i][j] += av[i] * bv[j];
        }
        if (more) {
            int nb = cur ^ 1;
            sm->A[nb][ak+0][am] = ra0.x; sm->A[nb][ak+1][am] = ra0.y;
            sm->A[nb][ak+2][am] = ra0.z; sm->A[nb][ak+3][am] = ra0.w;
            sm->A[nb][ak+0][am+64] = ra1.x; sm->A[nb][ak+1][am+64] = ra1.y;
            sm->A[nb][ak+2][am+64] = ra1.z; sm->A[nb][ak+3][am+64] = ra1.w;
            if (BT) {
                sm->B[nb][ak+0][am] = rb0.x; sm->B[nb][ak+1][am] = rb0.y;
                sm->B[nb][ak+2][am] = rb0.z; sm->B[nb][ak+3][am] = rb0.w;
                sm->B[nb][ak+0][am+64] = rb1.x; sm->B[nb][ak+1][am+64] = rb1.y;
                sm->B[nb][ak+2][am+64] = rb1.z; sm->B[nb][ak+3][am+64] = rb1.w;
            } else {
                *(float4*)&sm->B[nb][bk][bn]     = rb0;
                *(float4*)&sm->B[nb][bk + 8][bn] = rb1;
            }
        }
        __syncthreads();
    }
}

__device__ __forceinline__ void epilogue128(float* __restrict__ C, int ldc,
                                            int m0, int n0, float acc[8][8]) {
    int tid = threadIdx.x;
    int ty = tid >> 4, tx = tid & 15;
#pragma unroll
    for (int i = 0; i < 8; i++) {
        int row = m0 + (i < 4 ? ty * 4 + i : 64 + ty * 4 + (i - 4));
        float* cr = C + (size_t)row * ldc;
        *(float4*)&cr[n0 + tx * 4] =
            make_float4(acc[i][0], acc[i][1], acc[i][2], acc[i][3]);
        *(float4*)&cr[n0 + 64 + tx * 4] =
            make_float4(acc[i][4], acc[i][5], acc[i][6], acc[i][7]);
    }
}

// ---------------- K3a: q = rh @ Wm[h]  (per b,h) ----------------------------
__global__ __launch_bounds__(256) void q_kernel(const float* __restrict__ weight_m)
{
    __shared__ SmemGemm sm;
    int z = blockIdx.z;  int b = z >> 2, h = z & 3;
    int m0 = blockIdx.y * 128, n0 = blockIdx.x * 128;
    const float* A = &g_rh[b][m0][0];
    const float* B = weight_m + (size_t)h * DDIM * DDIM + n0;
    float acc[8][8] = {};
    gemm128_run<false>(&sm, A, DDIM, B, DDIM, DDIM / 16, acc);
    epilogue128(&g_q[z][0][0], DDIM, m0, n0, acc);
}

// ---------------- K3b: scores = q @ rh^T  (per b,h) -------------------------
__global__ __launch_bounds__(256) void scores_kernel()
{
    __shared__ SmemGemm sm;
    int z = blockIdx.z;  int b = z >> 2;
    int m0 = blockIdx.y * 128, n0 = blockIdx.x * 128;
    const float* A = &g_q[z][m0][0];
    const float* B = &g_rh[b][n0][0];
    float acc[8][8] = {};
    gemm128_run<true>(&sm, A, DDIM, B, DDIM, DDIM / 16, acc);
    epilogue128(&g_alpha[z][0][0], SLEN, m0, n0, acc);
}

// ---------------- K3d: sacc = alphaw @ rh  (per b) --------------------------
__global__ __launch_bounds__(256) void out_kernel()
{
    __shared__ SmemGemm sm;
    int b = blockIdx.z;
    int m0 = blockIdx.y * 128, n0 = blockIdx.x * 128;
    const float* A = &g_alphaw[b][m0][0];
    const float* B = &g_rh[b][0][n0];
    float acc[8][8] = {};
    gemm128_run<false>(&sm, A, SLEN, B, DDIM, SLEN / 16, acc);
    epilogue128(&g_sacc[b][0][0], DDIM, m0, n0, acc);
}

// ---------------- K1: embedding gather + input-gate GEMM --------------------
__device__ __forceinline__ void mm16(const float (*As)[68], const float (*Bs)[68],
                                     float acc[4][4], int ty, int tx) {
#pragma unroll
    for (int k = 0; k < 16; k++) {
        float4 a = *(const float4*)(&As[k][ty * 4]);
        float4 b = *(const float4*)(&Bs[k][tx * 4]);
        float ar[4] = {a.x, a.y, a.z, a.w};
        float br[4] = {b.x, b.y, b.z, b.w};
#pragma unroll
        for (int i = 0; i < 4; i++)
#pragma unroll
            for (int j = 0; j < 4; j++)
                acc[i][j] += ar[i] * br[j];
    }
}

__global__ __launch_bounds__(256) void gx_kernel(
    const void* __restrict__ review, const float* __restrict__ emb,
    const float* __restrict__ w_ih_f, const float* __restrict__ b_ih_f,
    const float* __restrict__ w_ih_b, const float* __restrict__ b_ih_b)
{
    __shared__ __align__(16) float As[16][68];
    __shared__ __align__(16) float Bs[16][68];
    int dir = blockIdx.z;
    const float* W    = dir ? w_ih_b : w_ih_f;
    const float* bias = dir ? b_ih_b : b_ih_f;
    int tid = threadIdx.x;
    int m0 = blockIdx.y * 64, n0 = blockIdx.x * 64;
    int lr = tid >> 2, kq = (tid & 3) * 4;

    int m = m0 + lr;
    int s = m >> 4, bb = m & 15;
    int stok = dir ? (SLEN - 1 - s) : s;
    long long tok;
    if (g_is64) tok = ((const long long*)review)[bb * SLEN + stok];
    else        tok = (long long)(((const int*)review)[bb * SLEN + stok]);
    const float* arow = emb + (size_t)tok * EDIM;
    const float* brow = W + (size_t)(n0 + lr) * EDIM;

    int ty = tid >> 4, tx = tid & 15;
    float acc[4][4] = {};
    for (int k0 = 0; k0 < EDIM; k0 += 16) {
#pragma unroll
        for (int i = 0; i < 4; i++) {
            int k = k0 + kq + i;
            As[kq + i][lr] = (k < EDIM) ? arow[k] : 0.f;
            Bs[kq + i][lr] = (k < EDIM) ? brow[k] : 0.f;
        }
        __syncthreads();
        mm16(As, Bs, acc, ty, tx);
        __syncthreads();
    }
#pragma unroll
    for (int i = 0; i < 4; i++) {
        int mm = m0 + ty * 4 + i;
        int ss = mm >> 4, bv = mm & 15;
#pragma unroll
        for (int j = 0; j < 4; j++) {
            int n = n0 + tx * 4 + j;
            g_gx[dir][ss][bv][n] = acc[i][j] + bias[n];
        }
    }
}

// ---------------- K2: GRU scan (one CTA per direction x batch) --------------
__global__ __launch_bounds__(512, 1) void gru_kernel(
    const float* __restrict__ w_hh_f, const float* __restrict__ b_hh_f,
    const float* __restrict__ w_hh_b, const float* __restrict__ b_hh_b)
{
    int dir = blockIdx.x >> 4;
    int b   = blockIdx.x & 15;
    const float* w_hh = dir ? w_hh_b : w_hh_f;
    const float* b_hh = dir ? b_hh_b : b_hh_f;

    int t  = threadIdx.x;     // 512 threads
    int jj = t >> 2;          // hidden unit 0..127
    int r4 = t & 3;           // k-quarter 0..3
    int k0 = r4 * 32;

    float wr[32], wz[32], wn[32];
#pragma unroll
    for (int i = 0; i < 32; i++) {
        wr[i] = w_hh[(jj)       * HDIM + k0 + i];
        wz[i] = w_hh[(HDIM + jj) * HDIM + k0 + i];
        wn[i] = w_hh[(2*HDIM+jj) * HDIM + k0 + i];
    }
    float bhr = 0.f, bhz = 0.f, bhn = 0.f, gxr = 0.f, gxz = 0.f, gxn = 0.f;
    const float* gx = &g_gx[dir][0][b][0];
    const int GXS = BATCH * G3;
    if (r4 == 0) {
        bhr = b_hh[jj]; bhz = b_hh[HDIM + jj]; bhn = b_hh[2*HDIM + jj];
        gxr = gx[jj]; gxz = gx[HDIM + jj]; gxn = gx[2*HDIM + jj];
    }

    __shared__ __align__(16) float h_sm[HDIM];
    if (t < HDIM) h_sm[t] = 0.f;
    __syncthreads();

    for (int sc = 0; sc < SLEN; sc++) {
        float ar = 0.f, az = 0.f, an = 0.f;
#pragma unroll
        for (int i = 0; i < 32; i += 4) {
            float4 v = *(const float4*)&h_sm[k0 + i];
            ar += wr[i]   * v.x; az += wz[i]   * v.x; an += wn[i]   * v.x;
            ar += wr[i+1] * v.y; az += wz[i+1] * v.y; an += wn[i+1] * v.y;
            ar += wr[i+2] * v.z; az += wz[i+2] * v.z; an += wn[i+2] * v.z;
            ar += wr[i+3] * v.w; az += wz[i+3] * v.w; an += wn[i+3] * v.w;
        }
        float hold = 0.f;
        if (r4 == 0) hold = h_sm[jj];

        ar += __shfl_xor_sync(0xffffffffu, ar, 1);
        ar += __shfl_xor_sync(0xffffffffu, ar, 2);
        az += __shfl_xor_sync(0xffffffffu, az, 1);
        az += __shfl_xor_sync(0xffffffffu, az, 2);
        an += __shfl_xor_sync(0xffffffffu, an, 1);
        an += __shfl_xor_sync(0xffffffffu, an, 2);

        __syncthreads();   // all reads of h_sm done
        if (r4 == 0) {
            float r = 1.f / (1.f + __expf(-(gxr + ar + bhr)));
            float z = 1.f / (1.f + __expf(-(gxz + az + bhz)));
            float n = tanhf(gxn + r * (an + bhn));
            float hnew = (1.f - z) * n + z * hold;
            h_sm[jj] = hnew;
            int sorig = dir ? (SLEN - 1 - sc) : sc;
            g_rh[b][sorig][dir * HDIM + jj] = hnew;
            if (sc + 1 < SLEN) {
                const float* g2 = gx + (size_t)(sc + 1) * GXS;
                gxr = g2[jj]; gxz = g2[HDIM + jj]; gxn = g2[2*HDIM + jj];
            }
        }
        __syncthreads();   // new h visible
    }
}

// ---------------- K3c: masked softmax over t + head-weight folding ----------
__device__ __forceinline__ float block_max(float v, float* red) {
#pragma unroll
    for (int o = 16; o; o >>= 1) v = fmaxf(v, __shfl_xor_sync(0xffffffffu, v, o));
    if ((threadIdx.x & 31) == 0) red[threadIdx.x >> 5] = v;
    __syncthreads();
    float r = red[0];
#pragma unroll
    for (int w = 1; w < 8; w++) r = fmaxf(r, red[w]);
    __syncthreads();
    return r;
}
__device__ __forceinline__ float block_sum(float v, float* red) {
#pragma unroll
    for (int o = 16; o; o >>= 1) v += __shfl_xor_sync(0xffffffffu, v, o);
    if ((threadIdx.x & 31) == 0) red[threadIdx.x >> 5] = v;
    __syncthreads();
    float r = red[0];
#pragma unroll
    for (int w = 1; w < 8; w++) r += red[w];
    __syncthreads();
    return r;
}

__global__ __launch_bounds__(256) void softmax_kernel(
    const float* __restrict__ mask, const float* __restrict__ wt_w)
{
    int bs = blockIdx.x;
    int b = bs >> 10, s = bs & 1023;
    int tid = threadIdx.x;
    __shared__ float smadd[SLEN];
    __shared__ float red[8];
    for (int i = tid; i < SLEN; i += 256)
        smadd[i] = (mask[b * SLEN + i] - 1.0f) * 1e11f;
    __syncthreads();

    float accw[4] = {0.f, 0.f, 0.f, 0.f};
    for (int h = 0; h < NHEADS; h++) {
        const float* row = &g_alpha[b * NHEADS + h][s][0];
        float v[4];
        float m = -INFINITY;
#pragma unroll
        for (int i = 0; i < 4; i++) {
            v[i] = row[tid + 256 * i] + smadd[tid + 256 * i];
            m = fmaxf(m, v[i]);
        }
        m = block_max(m, red);
        float ssum = 0.f;
#pragma unroll
        for (int i = 0; i < 4; i++) { v[i] = __expf(v[i] - m); ssum += v[i]; }
        ssum = block_sum(ssum, red);
        float w = wt_w[h] / ssum;
#pragma unroll
        for (int i = 0; i < 4; i++) accw[i] += w * v[i];
    }
    float* o = &g_alphaw[b][s][0];
#pragma unroll
    for (int i = 0; i < 4; i++) o[tid + 256 * i] = accw[i];
}

// ---------------- K4: final projection + log_softmax + mask -----------------
__global__ __launch_bounds__(256) void final_kernel(
    const float* __restrict__ wr_w, const float* __restrict__ wr_b,
    const float* __restrict__ wt_b, const float* __restrict__ mask,
    float* __restrict__ out)
{
    int warp = (blockIdx.x * blockDim.x + threadIdx.x) >> 5;
    if (warp >= BATCH * SLEN) return;
    int lane = threadIdx.x & 31;
    int b = warp >> 10, s = warp & 1023;
    const float* sa = &g_sacc[b][s][0];
    float tb = wt_b[0];
    float a0 = 0.f, a1 = 0.f, a2 = 0.f;
    for (int d = lane; d < DDIM; d += 32) {
        float v = sa[d] + tb;
        a0 += v * wr_w[d];
        a1 += v * wr_w[DDIM + d];
        a2 += v * wr_w[2 * DDIM + d];
    }
#pragma unroll
    for (int o = 16; o; o >>= 1) {
        a0 += __shfl_xor_sync(0xffffffffu, a0, o);
        a1 += __shfl_xor_sync(0xffffffffu, a1, o);
        a2 += __shfl_xor_sync(0xffffffffu, a2, o);
    }
    if (lane == 0) {
        a0 += wr_b[0]; a1 += wr_b[1]; a2 += wr_b[2];
        float m = fmaxf(a0, fmaxf(a1, a2));
        float lse = m + logf(expf(a0 - m) + expf(a1 - m) + expf(a2 - m));
        float mk = mask[b * SLEN + s];
        float* op = out + (size_t)(b * SLEN + s) * 3;
        op[0] = (a0 - lse) * mk;
        op[1] = (a1 - lse) * mk;
        op[2] = (a2 - lse) * mk;
    }
}

// ---------------- launch ----------------------------------------------------
extern "C" void kernel_launch(void* const* d_in, const int* in_sizes, int n_in,
                              void* d_out, int out_size)
{
    (void)in_sizes; (void)n_in; (void)out_size;
    const void*  review = d_in[0];
    const float* mask   = (const float*)d_in[2];
    const float* emb    = (const float*)d_in[3];
    const float* w_ih_f = (const float*)d_in[4];
    const float* w_hh_f = (const float*)d_in[5];
    const float* b_ih_f = (const float*)d_in[6];
    const float* b_hh_f = (const float*)d_in[7];
    const float* w_ih_b = (const float*)d_in[8];
    const float* w_hh_b = (const float*)d_in[9];
    const float* b_ih_b = (const float*)d_in[10];
    const float* b_hh_b = (const float*)d_in[11];
    const float* weight_m = (const float*)d_in[12];
    const float* wt_w   = (const float*)d_in[13];
    const float* wt_b   = (const float*)d_in[14];
    const float* wr_w   = (const float*)d_in[15];
    const float* wr_b   = (const float*)d_in[16];
    float* out = (float*)d_out;

    detect_kernel<<<1, 256>>>((const int*)review);
    gx_kernel<<<dim3(G3 / 64, (BATCH * SLEN) / 64, 2), 256>>>(
        review, emb, w_ih_f, b_ih_f, w_ih_b, b_ih_b);
    gru_kernel<<<32, 512>>>(w_hh_f, b_hh_f, w_hh_b, b_hh_b);
    q_kernel<<<dim3(DDIM / 128, SLEN / 128, BATCH * NHEADS), 256>>>(weight_m);
    scores_kernel<<<dim3(SLEN / 128, SLEN / 128, BATCH * NHEADS), 256>>>();
    softmax_kernel<<<BATCH * SLEN, 256>>>(mask, wt_w);
    out_kernel<<<dim3(DDIM / 128, SLEN / 128, BATCH), 256>>>();
    final_kernel<<<(BATCH * SLEN) / 8, 256>>>(wr_w, wr_b, wt_b, mask, out);
}

// round 9
// speedup vs baseline: 1.2201x; 1.1192x over previous
#include <cuda_runtime.h>
#include <cuda_bf16.h>
#include <stdint.h>
#include <math.h>

typedef unsigned int       u32;
typedef unsigned long long u64;

#define SLEN  1024
#define BATCH 16
#define EDIM  300
#define HDIM  128
#define G3    384
#define NHEADS 4
#define DDIM  256

// ---------------- scratch (device globals; no allocation allowed) ----------
__device__ __align__(16) float g_gx[2][SLEN][BATCH][G3];
__device__ __align__(16) float g_rh[BATCH][SLEN][DDIM];
__device__ __align__(16) float g_q[BATCH*NHEADS][SLEN][DDIM];
__device__ __align__(16) float g_alpha[BATCH*NHEADS][SLEN][SLEN];
__device__ __align__(16) float g_alphaw[BATCH][SLEN][SLEN];
__device__ __align__(16) float g_sacc[BATCH][SLEN][DDIM];
__device__ __align__(16) __nv_bfloat16 g_qh[BATCH*NHEADS][SLEN][DDIM];
__device__ __align__(16) __nv_bfloat16 g_ql[BATCH*NHEADS][SLEN][DDIM];
__device__ __align__(16) __nv_bfloat16 g_rhh[BATCH][SLEN][DDIM];
__device__ __align__(16) __nv_bfloat16 g_rhl[BATCH][SLEN][DDIM];
__device__ int g_is64;

// ---------------- dtype detection for `review` (int32 vs int64) ------------
__global__ void detect_kernel(const int* __restrict__ rv) {
    __shared__ int any;
    if (threadIdx.x == 0) any = 0;
    __syncthreads();
    int nz = 0;
    for (int j = threadIdx.x; j < BATCH * SLEN; j += blockDim.x)
        nz |= (rv[2 * j + 1] != 0);
    if (nz) atomicOr(&any, 1);
    __syncthreads();
    if (threadIdx.x == 0) g_is64 = any ? 0 : 1;
}

// ==================== warp-level MMA helpers (portable sm_80+) ==============
static __device__ __forceinline__ u32 smem_u32(const void* p) {
    u32 a;
    asm("{ .reg .u64 t; cvta.to.shared.u64 t, %1; cvt.u32.u64 %0, t; }" : "=r"(a) : "l"(p));
    return a;
}
static __device__ __forceinline__ void ldsm4(u32* r, u32 addr) {
    asm volatile("ldmatrix.sync.aligned.m8n8.x4.shared.b16 {%0,%1,%2,%3}, [%4];"
                 : "=r"(r[0]), "=r"(r[1]), "=r"(r[2]), "=r"(r[3]) : "r"(addr));
}
static __device__ __forceinline__ void mma_bf16(float* c, u32 a0, u32 a1, u32 a2, u32 a3,
                                                u32 b0, u32 b1) {
    asm volatile(
        "mma.sync.aligned.m16n8k16.row.col.f32.bf16.bf16.f32 "
        "{%0,%1,%2,%3}, {%4,%5,%6,%7}, {%8,%9}, {%0,%1,%2,%3};"
        : "+f"(c[0]), "+f"(c[1]), "+f"(c[2]), "+f"(c[3])
        : "r"(a0), "r"(a1), "r"(a2), "r"(a3), "r"(b0), "r"(b1));
}

// ---------------- bf16 hi/lo split ------------------------------------------
__global__ __launch_bounds__(256) void split_kernel(
    const float* __restrict__ src, __nv_bfloat16* __restrict__ hi,
    __nv_bfloat16* __restrict__ lo, int n4)
{
    int i = blockIdx.x * blockDim.x + threadIdx.x;
    if (i >= n4) return;
    float4 v = ((const float4*)src)[i];
    float x0 = v.x, x1 = v.y, x2 = v.z, x3 = v.w;
    __nv_bfloat16 h0 = __float2bfloat16(x0);
    __nv_bfloat16 h1 = __float2bfloat16(x1);
    __nv_bfloat16 h2 = __float2bfloat16(x2);
    __nv_bfloat16 h3 = __float2bfloat16(x3);
    __nv_bfloat16 l0 = __float2bfloat16(x0 - __bfloat162float(h0));
    __nv_bfloat16 l1 = __float2bfloat16(x1 - __bfloat162float(h1));
    __nv_bfloat16 l2 = __float2bfloat16(x2 - __bfloat162float(h2));
    __nv_bfloat16 l3 = __float2bfloat16(x3 - __bfloat162float(h3));
    ushort4 hv, lv;
    hv.x = *(unsigned short*)&h0; hv.y = *(unsigned short*)&h1;
    hv.z = *(unsigned short*)&h2; hv.w = *(unsigned short*)&h3;
    lv.x = *(unsigned short*)&l0; lv.y = *(unsigned short*)&l1;
    lv.z = *(unsigned short*)&l2; lv.w = *(unsigned short*)&l3;
    ((ushort4*)hi)[i] = hv;
    ((ushort4*)lo)[i] = lv;
}

// ---------------- K3b: scores via mma.sync bf16-split -----------------------
// per (b,h) 128x128 tile: alpha = qh.rhh^T + qh.rhl^T + ql.rhh^T
#define SROW 72                      // padded bf16 row stride (144B, conflict-free)
#define STILE (128 * SROW)
#define SMEM_MMA_BYTES (4 * STILE * 2)   // 73728

__global__ __launch_bounds__(256) void scores_mma_kernel()
{
    extern __shared__ char smraw[];
    __nv_bfloat16* S  = (__nv_bfloat16*)smraw;
    __nv_bfloat16* Ah = S;
    __nv_bfloat16* Al = S + STILE;
    __nv_bfloat16* Bh = S + 2 * STILE;
    __nv_bfloat16* Bl = S + 3 * STILE;

    int tid = threadIdx.x, wid = tid >> 5, lane = tid & 31;
    int z = blockIdx.z, b = z >> 2;
    int m0 = blockIdx.y * 128, n0 = blockIdx.x * 128;
    int wm = (wid >> 2) * 64, wn = (wid & 3) * 32;

    const __nv_bfloat16* gAh = &g_qh[z][m0][0];
    const __nv_bfloat16* gAl = &g_ql[z][m0][0];
    const __nv_bfloat16* gBh = &g_rhh[b][n0][0];
    const __nv_bfloat16* gBl = &g_rhl[b][n0][0];

    float acc[4][4][4];
#pragma unroll
    for (int mt = 0; mt < 4; mt++)
#pragma unroll
        for (int nt = 0; nt < 4; nt++)
#pragma unroll
            for (int e = 0; e < 4; e++)
                acc[mt][nt][e] = 0.f;

    int lrow = tid >> 3;
    int lc8  = (tid & 7) * 8;

    for (int kc = 0; kc < DDIM; kc += 64) {
        __syncthreads();
#pragma unroll
        for (int i = 0; i < 4; i++) {
            int row = lrow + i * 32;
            size_t g = (size_t)row * DDIM + kc + lc8;
            int s = row * SROW + lc8;
            *(uint4*)&Ah[s] = *(const uint4*)&gAh[g];
            *(uint4*)&Al[s] = *(const uint4*)&gAl[g];
            *(uint4*)&Bh[s] = *(const uint4*)&gBh[g];
            *(uint4*)&Bl[s] = *(const uint4*)&gBl[g];
        }
        __syncthreads();

#pragma unroll
        for (int ks = 0; ks < 4; ks++) {
            int k0 = ks * 16;
            u32 bh[2][4], bl[2][4];
#pragma unroll
            for (int p = 0; p < 2; p++) {
                int n  = wn + p * 16 + ((lane >> 4) << 3) + (lane & 7);
                int kk = k0 + (((lane >> 3) & 1) << 3);
                ldsm4(bh[p], smem_u32(&Bh[n * SROW + kk]));
                ldsm4(bl[p], smem_u32(&Bl[n * SROW + kk]));
            }
#pragma unroll
            for (int mt = 0; mt < 4; mt++) {
                int r  = wm + mt * 16 + (lane & 15);
                int kk = k0 + ((lane >> 4) << 3);
                u32 ah[4], al[4];
                ldsm4(ah, smem_u32(&Ah[r * SROW + kk]));
                ldsm4(al, smem_u32(&Al[r * SROW + kk]));
#pragma unroll
                for (int nt = 0; nt < 4; nt++) {
                    u32* bhp = &bh[nt >> 1][(nt & 1) * 2];
                    u32* blp = &bl[nt >> 1][(nt & 1) * 2];
                    mma_bf16(acc[mt][nt], ah[0], ah[1], ah[2], ah[3], bhp[0], bhp[1]);
                    mma_bf16(acc[mt][nt], ah[0], ah[1], ah[2], ah[3], blp[0], blp[1]);
                    mma_bf16(acc[mt][nt], al[0], al[1], al[2], al[3], bhp[0], bhp[1]);
                }
            }
        }
    }

    // epilogue: fragment layout c0,c1 -> (row=group, col=2*tig); c2,c3 -> row+8
    int group = lane >> 2, tig = lane & 3;
#pragma unroll
    for (int mt = 0; mt < 4; mt++) {
#pragma unroll
        for (int nt = 0; nt < 4; nt++) {
            int row = m0 + wm + mt * 16 + group;
            int col = n0 + wn + nt * 8 + tig * 2;
            float2 w0, w1;
            w0.x = acc[mt][nt][0]; w0.y = acc[mt][nt][1];
            w1.x = acc[mt][nt][2]; w1.y = acc[mt][nt][3];
            *(float2*)&g_alpha[z][row][col]     = w0;
            *(float2*)&g_alpha[z][row + 8][col] = w1;
        }
    }
}

// ============ 128x128 double-buffered fp32 GEMM (8x8 microtile, NN) =========
struct SmemGemm {
    float A[2][16][132];
    float B[2][16][132];
};

static __device__ __forceinline__ void gemm128_nn(
    SmemGemm* sm,
    const float* __restrict__ Abase, int lda,
    const float* __restrict__ Bbase, int ldb,
    int Ktiles, float acc[8][8])
{
    int tid = threadIdx.x;
    int am = tid >> 2;
    int ak = (tid & 3) * 4;
    int bk = tid >> 5;
    int bn = (tid & 31) * 4;
    int ty = tid >> 4, tx = tid & 15;

    float4 ra0, ra1, rb0, rb1;
    ra0 = *(const float4*)&Abase[(size_t)am * lda + ak];
    ra1 = *(const float4*)&Abase[(size_t)(am + 64) * lda + ak];
    rb0 = *(const float4*)&Bbase[(size_t)bk * ldb + bn];
    rb1 = *(const float4*)&Bbase[(size_t)(bk + 8) * ldb + bn];

    sm->A[0][ak+0][am] = ra0.x; sm->A[0][ak+1][am] = ra0.y;
    sm->A[0][ak+2][am] = ra0.z; sm->A[0][ak+3][am] = ra0.w;
    sm->A[0][ak+0][am+64] = ra1.x; sm->A[0][ak+1][am+64] = ra1.y;
    sm->A[0][ak+2][am+64] = ra1.z; sm->A[0][ak+3][am+64] = ra1.w;
    *(float4*)&sm->B[0][bk][bn]     = rb0;
    *(float4*)&sm->B[0][bk + 8][bn] = rb1;
    __syncthreads();

    for (int t = 0; t < Ktiles; t++) {
        int cur = t & 1;
        bool more = (t + 1 < Ktiles);
        if (more) {
            int koff = (t + 1) * 16;
            ra0 = *(const float4*)&Abase[(size_t)am * lda + ak + koff];
            ra1 = *(const float4*)&Abase[(size_t)(am + 64) * lda + ak + koff];
            rb0 = *(const float4*)&Bbase[(size_t)(bk + koff) * ldb + bn];
            rb1 = *(const float4*)&Bbase[(size_t)(bk + 8 + koff) * ldb + bn];
        }
#pragma unroll
        for (int k = 0; k < 16; k++) {
            float4 a0 = *(const float4*)&sm->A[cur][k][ty * 4];
            float4 a1 = *(const float4*)&sm->A[cur][k][64 + ty * 4];
            float4 b0 = *(const float4*)&sm->B[cur][k][tx * 4];
            float4 b1 = *(const float4*)&sm->B[cur][k][64 + tx * 4];
            float av[8], bv[8];
            av[0] = a0.x; av[1] = a0.y; av[2] = a0.z; av[3] = a0.w;
            av[4] = a1.x; av[5] = a1.y; av[6] = a1.z; av[7] = a1.w;
            bv[0] = b0.x; bv[1] = b0.y; bv[2] = b0.z; bv[3] = b0.w;
            bv[4] = b1.x; bv[5] = b1.y; bv[6] = b1.z; bv[7] = b1.w;
#pragma unroll
            for (int i = 0; i < 8; i++) {
#pragma unroll
                for (int j = 0; j < 8; j++) {
                    acc[i][j] += av[i] * bv[j];
                }
            }
        }
        if (more) {
            int nb = cur ^ 1;
            sm->A[nb][ak+0][am] = ra0.x; sm->A[nb][ak+1][am] = ra0.y;
            sm->A[nb][ak+2][am] = ra0.z; sm->A[nb][ak+3][am] = ra0.w;
            sm->A[nb][ak+0][am+64] = ra1.x; sm->A[nb][ak+1][am+64] = ra1.y;
            sm->A[nb][ak+2][am+64] = ra1.z; sm->A[nb][ak+3][am+64] = ra1.w;
            *(float4*)&sm->B[nb][bk][bn]     = rb0;
            *(float4*)&sm->B[nb][bk + 8][bn] = rb1;
        }
        __syncthreads();
    }
}

static __device__ __forceinline__ void epilogue128(float* __restrict__ C, int ldc,
                                                   int m0, int n0, float acc[8][8]) {
    int tid = threadIdx.x;
    int ty = tid >> 4, tx = tid & 15;
#pragma unroll
    for (int i = 0; i < 8; i++) {
        int row = m0 + (i < 4 ? ty * 4 + i : 64 + ty * 4 + (i - 4));
        float* cr = C + (size_t)row * ldc;
        float4 w0, w1;
        w0.x = acc[i][0]; w0.y = acc[i][1]; w0.z = acc[i][2]; w0.w = acc[i][3];
        w1.x = acc[i][4]; w1.y = acc[i][5]; w1.z = acc[i][6]; w1.w = acc[i][7];
        *(float4*)&cr[n0 + tx * 4] = w0;
        *(float4*)&cr[n0 + 64 + tx * 4] = w1;
    }
}

// ---------------- K3a: q = rh @ Wm[h]  (per b,h) ----------------------------
__global__ __launch_bounds__(256) void q_kernel(const float* __restrict__ weight_m)
{
    __shared__ SmemGemm sm;
    int z = blockIdx.z;
    int b = z >> 2, h = z & 3;
    int m0 = blockIdx.y * 128, n0 = blockIdx.x * 128;
    const float* A = &g_rh[b][m0][0];
    const float* B = weight_m + (size_t)h * DDIM * DDIM + n0;
    float acc[8][8] = {};
    gemm128_nn(&sm, A, DDIM, B, DDIM, DDIM / 16, acc);
    epilogue128(&g_q[z][0][0], DDIM, m0, n0, acc);
}

// ---------------- K3d: sacc = alphaw @ rh  (per b) --------------------------
__global__ __launch_bounds__(256) void out_kernel()
{
    __shared__ SmemGemm sm;
    int b = blockIdx.z;
    int m0 = blockIdx.y * 128, n0 = blockIdx.x * 128;
    const float* A = &g_alphaw[b][m0][0];
    const float* B = &g_rh[b][0][n0];
    float acc[8][8] = {};
    gemm128_nn(&sm, A, SLEN, B, DDIM, SLEN / 16, acc);
    epilogue128(&g_sacc[b][0][0], DDIM, m0, n0, acc);
}

// ---------------- K1: embedding gather + input-gate GEMM --------------------
static __device__ __forceinline__ void mm16(const float (*As)[68], const float (*Bs)[68],
                                            float acc[4][4], int ty, int tx) {
#pragma unroll
    for (int k = 0; k < 16; k++) {
        float4 a = *(const float4*)(&As[k][ty * 4]);
        float4 b = *(const float4*)(&Bs[k][tx * 4]);
        float ar[4], br[4];
        ar[0] = a.x; ar[1] = a.y; ar[2] = a.z; ar[3] = a.w;
        br[0] = b.x; br[1] = b.y; br[2] = b.z; br[3] = b.w;
#pragma unroll
        for (int i = 0; i < 4; i++) {
#pragma unroll
            for (int j = 0; j < 4; j++) {
                acc[i][j] += ar[i] * br[j];
            }
        }
    }
}

__global__ __launch_bounds__(256) void gx_kernel(
    const void* __restrict__ review, const float* __restrict__ emb,
    const float* __restrict__ w_ih_f, const float* __restrict__ b_ih_f,
    const float* __restrict__ w_ih_b, const float* __restrict__ b_ih_b)
{
    __shared__ __align__(16) float As[16][68];
    __shared__ __align__(16) float Bs[16][68];
    int dir = blockIdx.z;
    const float* W    = dir ? w_ih_b : w_ih_f;
    const float* bias = dir ? b_ih_b : b_ih_f;
    int tid = threadIdx.x;
    int m0 = blockIdx.y * 64, n0 = blockIdx.x * 64;
    int lr = tid >> 2, kq = (tid & 3) * 4;

    int m = m0 + lr;
    int s = m >> 4, bb = m & 15;
    int stok = dir ? (SLEN - 1 - s) : s;
    long long tok;
    if (g_is64) tok = ((const long long*)review)[bb * SLEN + stok];
    else        tok = (long long)(((const int*)review)[bb * SLEN + stok]);
    const float* arow = emb + (size_t)tok * EDIM;
    const float* brow = W + (size_t)(n0 + lr) * EDIM;

    int ty = tid >> 4, tx = tid & 15;
    float acc[4][4] = {};
    for (int k0 = 0; k0 < EDIM; k0 += 16) {
#pragma unroll
        for (int i = 0; i < 4; i++) {
            int k = k0 + kq + i;
            As[kq + i][lr] = (k < EDIM) ? arow[k] : 0.f;
            Bs[kq + i][lr] = (k < EDIM) ? brow[k] : 0.f;
        }
        __syncthreads();
        mm16(As, Bs, acc, ty, tx);
        __syncthreads();
    }
#pragma unroll
    for (int i = 0; i < 4; i++) {
        int mm = m0 + ty * 4 + i;
        int ss = mm >> 4, bv = mm & 15;
#pragma unroll
        for (int j = 0; j < 4; j++) {
            int n = n0 + tx * 4 + j;
            g_gx[dir][ss][bv][n] = acc[i][j] + bias[n];
        }
    }
}

// ---------------- K2: GRU scan (one CTA per direction x batch) --------------
__global__ __launch_bounds__(512, 1) void gru_kernel(
    const float* __restrict__ w_hh_f, const float* __restrict__ b_hh_f,
    const float* __restrict__ w_hh_b, const float* __restrict__ b_hh_b)
{
    int dir = blockIdx.x >> 4;
    int b   = blockIdx.x & 15;
    const float* w_hh = dir ? w_hh_b : w_hh_f;
    const float* b_hh = dir ? b_hh_b : b_hh_f;

    int t  = threadIdx.x;
    int jj = t >> 2;
    int r4 = t & 3;
    int k0 = r4 * 32;

    float wr[32], wz[32], wn[32];
#pragma unroll
    for (int i = 0; i < 32; i++) {
        wr[i] = w_hh[(jj)        * HDIM + k0 + i];
        wz[i] = w_hh[(HDIM + jj) * HDIM + k0 + i];
        wn[i] = w_hh[(2*HDIM+jj) * HDIM + k0 + i];
    }
    float bhr = 0.f, bhz = 0.f, bhn = 0.f, gxr = 0.f, gxz = 0.f, gxn = 0.f;
    const float* gx = &g_gx[dir][0][b][0];
    const int GXS = BATCH * G3;
    if (r4 == 0) {
        bhr = b_hh[jj]; bhz = b_hh[HDIM + jj]; bhn = b_hh[2*HDIM + jj];
        gxr = gx[jj]; gxz = gx[HDIM + jj]; gxn = gx[2*HDIM + jj];
    }

    __shared__ __align__(16) float h_sm[HDIM];
    if (t < HDIM) h_sm[t] = 0.f;
    __syncthreads();

    for (int sc = 0; sc < SLEN; sc++) {
        float ar = 0.f, az = 0.f, an = 0.f;
#pragma unroll
        for (int i = 0; i < 32; i += 4) {
            float4 v = *(const float4*)&h_sm[k0 + i];
            ar += wr[i]   * v.x; az += wz[i]   * v.x; an += wn[i]   * v.x;
            ar += wr[i+1] * v.y; az += wz[i+1] * v.y; an += wn[i+1] * v.y;
            ar += wr[i+2] * v.z; az += wz[i+2] * v.z; an += wn[i+2] * v.z;
            ar += wr[i+3] * v.w; az += wz[i+3] * v.w; an += wn[i+3] * v.w;
        }
        float hold = 0.f;
        if (r4 == 0) hold = h_sm[jj];

        ar += __shfl_xor_sync(0xffffffffu, ar, 1);
        ar += __shfl_xor_sync(0xffffffffu, ar, 2);
        az += __shfl_xor_sync(0xffffffffu, az, 1);
        az += __shfl_xor_sync(0xffffffffu, az, 2);
        an += __shfl_xor_sync(0xffffffffu, an, 1);
        an += __shfl_xor_sync(0xffffffffu, an, 2);

        __syncthreads();
        if (r4 == 0) {
            float r = 1.f / (1.f + __expf(-(gxr + ar + bhr)));
            float z = 1.f / (1.f + __expf(-(gxz + az + bhz)));
            float n = tanhf(gxn + r * (an + bhn));
            float hnew = (1.f - z) * n + z * hold;
            h_sm[jj] = hnew;
            int sorig = dir ? (SLEN - 1 - sc) : sc;
            g_rh[b][sorig][dir * HDIM + jj] = hnew;
            if (sc + 1 < SLEN) {
                const float* g2 = gx + (size_t)(sc + 1) * GXS;
                gxr = g2[jj]; gxz = g2[HDIM + jj]; gxn = g2[2*HDIM + jj];
            }
        }
        __syncthreads();
    }
}

// ---------------- K3c: masked softmax over t + head-weight folding ----------
static __device__ __forceinline__ float block_max(float v, float* red) {
#pragma unroll
    for (int o = 16; o; o >>= 1) v = fmaxf(v, __shfl_xor_sync(0xffffffffu, v, o));
    if ((threadIdx.x & 31) == 0) red[threadIdx.x >> 5] = v;
    __syncthreads();
    float r = red[0];
#pragma unroll
    for (int w = 1; w < 8; w++) r = fmaxf(r, red[w]);
    __syncthreads();
    return r;
}
static __device__ __forceinline__ float block_sum(float v, float* red) {
#pragma unroll
    for (int o = 16; o; o >>= 1) v += __shfl_xor_sync(0xffffffffu, v, o);
    if ((threadIdx.x & 31) == 0) red[threadIdx.x >> 5] = v;
    __syncthreads();
    float r = red[0];
#pragma unroll
    for (int w = 1; w < 8; w++) r += red[w];
    __syncthreads();
    return r;
}

__global__ __launch_bounds__(256) void softmax_kernel(
    const float* __restrict__ mask, const float* __restrict__ wt_w)
{
    int bs = blockIdx.x;
    int b = bs >> 10, s = bs & 1023;
    int tid = threadIdx.x;
    __shared__ float smadd[SLEN];
    __shared__ float red[8];
    for (int i = tid; i < SLEN; i += 256)
        smadd[i] = (mask[b * SLEN + i] - 1.0f) * 1e11f;
    __syncthreads();

    float accw0 = 0.f, accw1 = 0.f, accw2 = 0.f, accw3 = 0.f;
    for (int h = 0; h < NHEADS; h++) {
        const float* row = &g_alpha[b * NHEADS + h][s][0];
        float v0 = row[tid]       + smadd[tid];
        float v1 = row[tid + 256] + smadd[tid + 256];
        float v2 = row[tid + 512] + smadd[tid + 512];
        float v3 = row[tid + 768] + smadd[tid + 768];
        float m = fmaxf(fmaxf(v0, v1), fmaxf(v2, v3));
        m = block_max(m, red);
        v0 = __expf(v0 - m); v1 = __expf(v1 - m);
        v2 = __expf(v2 - m); v3 = __expf(v3 - m);
        float ssum = block_sum(v0 + v1 + v2 + v3, red);
        float w = wt_w[h] / ssum;
        accw0 += w * v0; accw1 += w * v1; accw2 += w * v2; accw3 += w * v3;
    }
    float* o = &g_alphaw[b][s][0];
    o[tid] = accw0; o[tid + 256] = accw1; o[tid + 512] = accw2; o[tid + 768] = accw3;
}

// ---------------- K4: final projection + log_softmax + mask -----------------
__global__ __launch_bounds__(256) void final_kernel(
    const float* __restrict__ wr_w, const float* __restrict__ wr_b,
    const float* __restrict__ wt_b, const float* __restrict__ mask,
    float* __restrict__ out)
{
    int warp = (blockIdx.x * blockDim.x + threadIdx.x) >> 5;
    if (warp >= BATCH * SLEN) return;
    int lane = threadIdx.x & 31;
    int b = warp >> 10, s = warp & 1023;
    const float* sa = &g_sacc[b][s][0];
    float tb = wt_b[0];
    float a0 = 0.f, a1 = 0.f, a2 = 0.f;
    for (int d = lane; d < DDIM; d += 32) {
        float v = sa[d] + tb;
        a0 += v * wr_w[d];
        a1 += v * wr_w[DDIM + d];
        a2 += v * wr_w[2 * DDIM + d];
    }
#pragma unroll
    for (int o = 16; o; o >>= 1) {
        a0 += __shfl_xor_sync(0xffffffffu, a0, o);
        a1 += __shfl_xor_sync(0xffffffffu, a1, o);
        a2 += __shfl_xor_sync(0xffffffffu, a2, o);
    }
    if (lane == 0) {
        a0 += wr_b[0]; a1 += wr_b[1]; a2 += wr_b[2];
        float m = fmaxf(a0, fmaxf(a1, a2));
        float lse = m + logf(expf(a0 - m) + expf(a1 - m) + expf(a2 - m));
        float mk = mask[b * SLEN + s];
        float* op = out + (size_t)(b * SLEN + s) * 3;
        op[0] = (a0 - lse) * mk;
        op[1] = (a1 - lse) * mk;
        op[2] = (a2 - lse) * mk;
    }
}

// ---------------- launch ----------------------------------------------------
extern "C" void kernel_launch(void* const* d_in, const int* in_sizes, int n_in,
                              void* d_out, int out_size)
{
    (void)in_sizes; (void)n_in; (void)out_size;
    const void*  review = d_in[0];
    const float* mask   = (const float*)d_in[2];
    const float* emb    = (const float*)d_in[3];
    const float* w_ih_f = (const float*)d_in[4];
    const float* w_hh_f = (const float*)d_in[5];
    const float* b_ih_f = (const float*)d_in[6];
    const float* b_hh_f = (const float*)d_in[7];
    const float* w_ih_b = (const float*)d_in[8];
    const float* w_hh_b = (const float*)d_in[9];
    const float* b_ih_b = (const float*)d_in[10];
    const float* b_hh_b = (const float*)d_in[11];
    const float* weight_m = (const float*)d_in[12];
    const float* wt_w   = (const float*)d_in[13];
    const float* wt_b   = (const float*)d_in[14];
    const float* wr_w   = (const float*)d_in[15];
    const float* wr_b   = (const float*)d_in[16];
    float* out = (float*)d_out;

    // idempotent, deterministic, not stream-ordered (no static guards allowed)
    cudaFuncSetAttribute(scores_mma_kernel,
                         cudaFuncAttributeMaxDynamicSharedMemorySize, SMEM_MMA_BYTES);

    float* rh_flat = 0;
    float* q_flat = 0;
    __nv_bfloat16* rhh = 0;
    __nv_bfloat16* rhl = 0;
    __nv_bfloat16* qh = 0;
    __nv_bfloat16* ql = 0;
    cudaGetSymbolAddress((void**)&rh_flat, g_rh);
    cudaGetSymbolAddress((void**)&q_flat, g_q);
    cudaGetSymbolAddress((void**)&rhh, g_rhh);
    cudaGetSymbolAddress((void**)&rhl, g_rhl);
    cudaGetSymbolAddress((void**)&qh, g_qh);
    cudaGetSymbolAddress((void**)&ql, g_ql);

    detect_kernel<<<1, 256>>>((const int*)review);
    gx_kernel<<<dim3(G3 / 64, (BATCH * SLEN) / 64, 2), 256>>>(
        review, emb, w_ih_f, b_ih_f, w_ih_b, b_ih_b);
    gru_kernel<<<32, 512>>>(w_hh_f, b_hh_f, w_hh_b, b_hh_b);
    split_kernel<<<(BATCH * SLEN * DDIM / 4 + 255) / 256, 256>>>(
        rh_flat, rhh, rhl, BATCH * SLEN * DDIM / 4);
    q_kernel<<<dim3(DDIM / 128, SLEN / 128, BATCH * NHEADS), 256>>>(weight_m);
    split_kernel<<<(BATCH * NHEADS * SLEN * DDIM / 4 + 255) / 256, 256>>>(
        q_flat, qh, ql, BATCH * NHEADS * SLEN * DDIM / 4);
    scores_mma_kernel<<<dim3(SLEN / 128, SLEN / 128, BATCH * NHEADS), 256,
                        SMEM_MMA_BYTES>>>();
    softmax_kernel<<<BATCH * SLEN, 256>>>(mask, wt_w);
    out_kernel<<<dim3(DDIM / 128, SLEN / 128, BATCH), 256>>>();
    final_kernel<<<(BATCH * SLEN) / 8, 256>>>(wr_w, wr_b, wt_b, mask, out);
}